// round 3
// baseline (speedup 1.0000x reference)
#include <cuda_runtime.h>
#include <cuda_fp16.h>
#include <mma.h>

using namespace nvcuda;

// ---------------- problem constants ----------------
#define BB   16
#define SS   512
#define HH   768
#define NH_  12
#define DD   64
#define FF_  3072
#define LL   4
#define MR   (BB*SS)          // 8192 rows
#define SCALE_Q 0.125f        // D^-0.5
#define LN_EPS 1e-5f

#define HHxHH   (HH*HH)       // 589824
#define HHxFF   (HH*FF_)      // 2359296

// ---------------- scratch (__device__ globals; no cudaMalloc allowed) ----------------
__device__ __align__(16) float  g_h[(size_t)MR*HH];          // fp32 residual stream
__device__ __align__(16) __half g_y[(size_t)MR*HH];          // LN output (fp16)
__device__ __align__(16) __half g_q[(size_t)MR*HH];          // [B,NH,S,D]
__device__ __align__(16) __half g_k[(size_t)MR*HH];
__device__ __align__(16) __half g_v[(size_t)MR*HH];
__device__ __align__(16) __half g_attn[(size_t)MR*HH];       // attn out, [B,S,H]
__device__ __align__(16) float  g_scores[(size_t)BB*NH_*SS*SS];
__device__ __align__(16) __half g_probs [(size_t)BB*NH_*SS*SS];
__device__ __align__(16) __half g_ff[(size_t)MR*FF_];
// fp16 weights: [wq | wk | wv | wo | w1 | w2], each for all L layers
__device__ __align__(16) __half g_w16[(size_t)LL*(4*HHxHH + 2*HHxFF)];

// offsets (in halfs) into g_w16
#define OFF_WQ  ((size_t)0)
#define OFF_WK  ((size_t)LL*HHxHH)
#define OFF_WV  ((size_t)2*LL*HHxHH)
#define OFF_WO  ((size_t)3*LL*HHxHH)
#define OFF_W1  ((size_t)4*LL*HHxHH)
#define OFF_W2  ((size_t)4*LL*HHxHH + (size_t)LL*HHxFF)

// ---------------- small utility kernels ----------------
__global__ void copy_f4_kernel(const float* __restrict__ src, float* __restrict__ dst, int n4) {
    int i = blockIdx.x * blockDim.x + threadIdx.x;
    if (i < n4) reinterpret_cast<float4*>(dst)[i] = reinterpret_cast<const float4*>(src)[i];
}

__global__ void conv_f2h_kernel(const float* __restrict__ src, __half* __restrict__ dst, int n2) {
    int i = blockIdx.x * blockDim.x + threadIdx.x;
    if (i < n2) {
        float2 f = reinterpret_cast<const float2*>(src)[i];
        reinterpret_cast<__half2*>(dst)[i] = __floats2half2_rn(f.x, f.y);
    }
}

// ---------------- LayerNorm: one block (256 thr) per row of 768 ----------------
__global__ __launch_bounds__(256) void ln_kernel(
    const float* __restrict__ in, const float* __restrict__ g, const float* __restrict__ b,
    __half* __restrict__ outH, float* __restrict__ outF)
{
    const int row = blockIdx.x;
    const float* x = in + (size_t)row * HH;
    const int t = threadIdx.x;

    float v[3], s = 0.f, s2 = 0.f;
#pragma unroll
    for (int i = 0; i < 3; i++) {
        float xv = x[t + i * 256];
        v[i] = xv; s += xv; s2 += xv * xv;
    }
#pragma unroll
    for (int o = 16; o; o >>= 1) {
        s  += __shfl_xor_sync(0xffffffffu, s,  o);
        s2 += __shfl_xor_sync(0xffffffffu, s2, o);
    }
    __shared__ float r1[8], r2[8];
    __shared__ float mean_s, rstd_s;
    if ((t & 31) == 0) { r1[t >> 5] = s; r2[t >> 5] = s2; }
    __syncthreads();
    if (t == 0) {
        float ss = 0.f, ss2 = 0.f;
#pragma unroll
        for (int i = 0; i < 8; i++) { ss += r1[i]; ss2 += r2[i]; }
        float mean = ss * (1.f / HH);
        float var  = ss2 * (1.f / HH) - mean * mean;
        mean_s = mean;
        rstd_s = rsqrtf(var + LN_EPS);
    }
    __syncthreads();
    const float mean = mean_s, rstd = rstd_s;
#pragma unroll
    for (int i = 0; i < 3; i++) {
        int idx = t + i * 256;
        float o = (v[i] - mean) * rstd * g[idx] + b[idx];
        if (outH) outH[(size_t)row * HH + idx] = __float2half_rn(o);
        else      outF[(size_t)row * HH + idx] = o;
    }
}

// ---------------- softmax over rows of 512 (one block / row) ----------------
__global__ __launch_bounds__(256) void softmax_kernel(
    const float* __restrict__ sc, __half* __restrict__ pr)
{
    const size_t row = blockIdx.x;
    const float* x = sc + row * SS;
    __half* p = pr + row * SS;
    const int t = threadIdx.x;

    float a0 = x[t], a1 = x[t + 256];
    float m = fmaxf(a0, a1);
#pragma unroll
    for (int o = 16; o; o >>= 1) m = fmaxf(m, __shfl_xor_sync(0xffffffffu, m, o));
    __shared__ float rm[8];
    __shared__ float rowmax_s, rowsum_s;
    if ((t & 31) == 0) rm[t >> 5] = m;
    __syncthreads();
    if (t == 0) {
        float mm = rm[0];
#pragma unroll
        for (int i = 1; i < 8; i++) mm = fmaxf(mm, rm[i]);
        rowmax_s = mm;
    }
    __syncthreads();
    const float mx = rowmax_s;
    float e0 = __expf(a0 - mx), e1 = __expf(a1 - mx);
    float s = e0 + e1;
#pragma unroll
    for (int o = 16; o; o >>= 1) s += __shfl_xor_sync(0xffffffffu, s, o);
    __syncthreads();
    if ((t & 31) == 0) rm[t >> 5] = s;
    __syncthreads();
    if (t == 0) {
        float ssum = 0.f;
#pragma unroll
        for (int i = 0; i < 8; i++) ssum += rm[i];
        rowsum_s = ssum;
    }
    __syncthreads();
    const float inv = 1.f / rowsum_s;
    p[t]       = __float2half_rn(e0 * inv);
    p[t + 256] = __float2half_rn(e1 * inv);
}

// ---------------- generic wmma GEMM, 128x64 block tile, BK=16, 8 warps ----------------
// A: fp16 row-major [M,K], lda=K. B: fp16; BCOL=false -> row-major [K,N] (ldb);
// BCOL=true -> element(k,n) = Bg[n*ldb + k] (i.e. B^T where rows are n).
// Epilogues:
//  0 QKV : outH[((b*NH+h)*S+s)*D+d] = (acc + bias[col]) * oscale
//  1 SCR : outF[z*S*S + i*S + j] = acc + bias[z*S*S + i*S + j]   (bias = attn_bias)
//  2 PV  : outH[((b*S+i)*H) + h*D + j] = acc ,  z = b*NH+h
//  3 RES : outF[i*N + j] += acc + bias[j]
//  4 GEL : outH[i*N + j] = gelu(acc + bias[j])
template<int EPI, bool BCOL>
__global__ __launch_bounds__(256) void gemm_kernel(
    const __half* __restrict__ Ag, const __half* __restrict__ Bg,
    const float* __restrict__ bias,
    float* __restrict__ outF, __half* __restrict__ outH,
    int M, int N, int K, int ldb,
    long sA, long sB, float oscale)
{
    __shared__ __align__(16) __half As[128 * 24];
    __shared__ __align__(16) __half Bs[1600];          // row: 16*72=1152, col: 64*24=1536
    __shared__ __align__(16) float  Cs[128 * 68];

    const int z  = blockIdx.z;
    const __half* A  = Ag + (size_t)z * sA + (size_t)blockIdx.y * 128 * K;
    const __half* Bb = Bg + (size_t)z * sB;
    const int n0 = blockIdx.x * 64;

    const int t = threadIdx.x;
    const int w = t >> 5;
    const int wm = w >> 1, wn = w & 1;

    wmma::fragment<wmma::accumulator, 16, 16, 16, float> c[2][2];
#pragma unroll
    for (int i = 0; i < 2; i++)
#pragma unroll
        for (int j = 0; j < 2; j++) wmma::fill_fragment(c[i][j], 0.f);

    for (int k0 = 0; k0 < K; k0 += 16) {
        { // A tile 128x16
            int r = t >> 1, c8 = (t & 1) * 8;
            *reinterpret_cast<uint4*>(&As[r * 24 + c8]) =
                *reinterpret_cast<const uint4*>(A + (size_t)r * K + k0 + c8);
        }
        if (!BCOL) { // B tile 16x64 (row-major)
            if (t < 128) {
                int kk = t >> 3, j8 = (t & 7) * 8;
                *reinterpret_cast<uint4*>(&Bs[kk * 72 + j8]) =
                    *reinterpret_cast<const uint4*>(Bb + (size_t)(k0 + kk) * ldb + n0 + j8);
            }
        } else {     // B^T tile: 64 n-rows x 16 k
            if (t < 128) {
                int ni = t >> 1, k8 = (t & 1) * 8;
                *reinterpret_cast<uint4*>(&Bs[ni * 24 + k8]) =
                    *reinterpret_cast<const uint4*>(Bb + (size_t)(n0 + ni) * ldb + k0 + k8);
            }
        }
        __syncthreads();

        wmma::fragment<wmma::matrix_a, 16, 16, 16, __half, wmma::row_major> af[2];
#pragma unroll
        for (int i = 0; i < 2; i++)
            wmma::load_matrix_sync(af[i], &As[(wm * 32 + i * 16) * 24], 24);

        if (!BCOL) {
            wmma::fragment<wmma::matrix_b, 16, 16, 16, __half, wmma::row_major> bf[2];
#pragma unroll
            for (int j = 0; j < 2; j++)
                wmma::load_matrix_sync(bf[j], &Bs[wn * 32 + j * 16], 72);
#pragma unroll
            for (int i = 0; i < 2; i++)
#pragma unroll
                for (int j = 0; j < 2; j++)
                    wmma::mma_sync(c[i][j], af[i], bf[j], c[i][j]);
        } else {
            wmma::fragment<wmma::matrix_b, 16, 16, 16, __half, wmma::col_major> bf[2];
#pragma unroll
            for (int j = 0; j < 2; j++)
                wmma::load_matrix_sync(bf[j], &Bs[(wn * 32 + j * 16) * 24], 24);
#pragma unroll
            for (int i = 0; i < 2; i++)
#pragma unroll
                for (int j = 0; j < 2; j++)
                    wmma::mma_sync(c[i][j], af[i], bf[j], c[i][j]);
        }
        __syncthreads();
    }

    // stage accumulators to smem
#pragma unroll
    for (int i = 0; i < 2; i++)
#pragma unroll
        for (int j = 0; j < 2; j++)
            wmma::store_matrix_sync(&Cs[(wm * 32 + i * 16) * 68 + wn * 32 + j * 16],
                                    c[i][j], 68, wmma::mem_row_major);
    __syncthreads();

    // epilogue: 8192 elements / 256 threads
    const int gi0 = blockIdx.y * 128;
#pragma unroll 4
    for (int e = t; e < 128 * 64; e += 256) {
        int r  = e >> 6, cc = e & 63;
        float acc = Cs[r * 68 + cc];
        int gi = gi0 + r, gj = n0 + cc;

        if (EPI == 0) {
            float val = (acc + bias[gj]) * oscale;
            int bb = gi >> 9, ss = gi & 511, hh = gj >> 6, dd = gj & 63;
            outH[(((size_t)(bb * NH_ + hh) * SS + ss) << 6) + dd] = __float2half_rn(val);
        } else if (EPI == 1) {
            size_t idx = (size_t)z * SS * SS + (size_t)gi * SS + gj;
            outF[idx] = acc + bias[idx];
        } else if (EPI == 2) {
            int bb = z / NH_, hh = z - bb * NH_;
            outH[((size_t)(bb * SS + gi)) * HH + hh * DD + gj] = __float2half_rn(acc);
        } else if (EPI == 3) {
            size_t idx = (size_t)gi * N + gj;
            outF[idx] += acc + bias[gj];
        } else { // EPI == 4, exact gelu
            float xv = acc + bias[gj];
            float gl = 0.5f * xv * (1.f + erff(xv * 0.70710678118654752f));
            outH[(size_t)gi * N + gj] = __float2half_rn(gl);
        }
    }
}

// ---------------- host ----------------
extern "C" void kernel_launch(void* const* d_in, const int* in_sizes, int n_in,
                              void* d_out, int out_size)
{
    const float* x         = (const float*)d_in[0];
    const float* attn_bias = (const float*)d_in[1];
    const float* ln1_g = (const float*)d_in[2];
    const float* ln1_b = (const float*)d_in[3];
    const float* wq = (const float*)d_in[4];
    const float* bq = (const float*)d_in[5];
    const float* wk = (const float*)d_in[6];
    const float* bk = (const float*)d_in[7];
    const float* wv = (const float*)d_in[8];
    const float* bv = (const float*)d_in[9];
    const float* wo = (const float*)d_in[10];
    const float* bo = (const float*)d_in[11];
    const float* ln2_g = (const float*)d_in[12];
    const float* ln2_b = (const float*)d_in[13];
    const float* w1 = (const float*)d_in[14];
    const float* b1 = (const float*)d_in[15];
    const float* w2 = (const float*)d_in[16];
    const float* b2 = (const float*)d_in[17];
    const float* fln_g = (const float*)d_in[18];
    const float* fln_b = (const float*)d_in[19];
    float* out = (float*)d_out;

    void* pv_ = nullptr;
    cudaGetSymbolAddress(&pv_, g_h);      float*  p_h    = (float*)pv_;
    cudaGetSymbolAddress(&pv_, g_y);      __half* p_y    = (__half*)pv_;
    cudaGetSymbolAddress(&pv_, g_q);      __half* p_q    = (__half*)pv_;
    cudaGetSymbolAddress(&pv_, g_k);      __half* p_k    = (__half*)pv_;
    cudaGetSymbolAddress(&pv_, g_v);      __half* p_v    = (__half*)pv_;
    cudaGetSymbolAddress(&pv_, g_attn);   __half* p_attn = (__half*)pv_;
    cudaGetSymbolAddress(&pv_, g_scores); float*  p_sc   = (float*)pv_;
    cudaGetSymbolAddress(&pv_, g_probs);  __half* p_pr   = (__half*)pv_;
    cudaGetSymbolAddress(&pv_, g_ff);     __half* p_ff   = (__half*)pv_;
    cudaGetSymbolAddress(&pv_, g_w16);    __half* p_w16  = (__half*)pv_;

    __half* wq16 = p_w16 + OFF_WQ;
    __half* wk16 = p_w16 + OFF_WK;
    __half* wv16 = p_w16 + OFF_WV;
    __half* wo16 = p_w16 + OFF_WO;
    __half* w116 = p_w16 + OFF_W1;
    __half* w216 = p_w16 + OFF_W2;

    // h = x
    {
        int n4 = MR * HH / 4;
        copy_f4_kernel<<<(n4 + 255) / 256, 256>>>(x, p_h, n4);
    }
    // convert weights fp32 -> fp16 (all layers at once)
    {
        int n2;
        n2 = LL * HHxHH / 2;
        conv_f2h_kernel<<<(n2 + 255) / 256, 256>>>(wq, wq16, n2);
        conv_f2h_kernel<<<(n2 + 255) / 256, 256>>>(wk, wk16, n2);
        conv_f2h_kernel<<<(n2 + 255) / 256, 256>>>(wv, wv16, n2);
        conv_f2h_kernel<<<(n2 + 255) / 256, 256>>>(wo, wo16, n2);
        n2 = LL * HHxFF / 2;
        conv_f2h_kernel<<<(n2 + 255) / 256, 256>>>(w1, w116, n2);
        conv_f2h_kernel<<<(n2 + 255) / 256, 256>>>(w2, w216, n2);
    }

    const dim3 blk(256);
    const dim3 grid_proj(HH / 64, MR / 128, 1);        // 12 x 64
    const dim3 grid_scr(SS / 64, SS / 128, BB * NH_);  // 8 x 4 x 192
    const dim3 grid_pv(DD / 64, SS / 128, BB * NH_);   // 1 x 4 x 192
    const dim3 grid_ff1(FF_ / 64, MR / 128, 1);        // 48 x 64

    for (int l = 0; l < LL; l++) {
        // LN1 -> y (fp16)
        ln_kernel<<<MR, blk>>>(p_h, ln1_g + l * HH, ln1_b + l * HH, p_y, nullptr);
        // Q,K,V projections (Q scaled by SCALE at write)
        gemm_kernel<0, false><<<grid_proj, blk>>>(p_y, wq16 + (size_t)l * HHxHH, bq + l * HH,
                                                  nullptr, p_q, MR, HH, HH, HH, 0, 0, SCALE_Q);
        gemm_kernel<0, false><<<grid_proj, blk>>>(p_y, wk16 + (size_t)l * HHxHH, bk + l * HH,
                                                  nullptr, p_k, MR, HH, HH, HH, 0, 0, 1.f);
        gemm_kernel<0, false><<<grid_proj, blk>>>(p_y, wv16 + (size_t)l * HHxHH, bv + l * HH,
                                                  nullptr, p_v, MR, HH, HH, HH, 0, 0, 1.f);
        // scores = qk^T + bias  (batched over B*NH)
        gemm_kernel<1, true><<<grid_scr, blk>>>(p_q, p_k, attn_bias,
                                                p_sc, nullptr, SS, SS, DD, DD,
                                                (long)SS * DD, (long)SS * DD, 1.f);
        // softmax
        softmax_kernel<<<(unsigned)(BB * NH_ * SS), blk>>>(p_sc, p_pr);
        // o = P @ V  (batched), scatter to [B,S,H]
        gemm_kernel<2, false><<<grid_pv, blk>>>(p_pr, p_v, nullptr,
                                                nullptr, p_attn, SS, DD, SS, DD,
                                                (long)SS * SS, (long)SS * DD, 1.f);
        // h += o @ Wo + bo
        gemm_kernel<3, false><<<grid_proj, blk>>>(p_attn, wo16 + (size_t)l * HHxHH, bo + l * HH,
                                                  p_h, nullptr, MR, HH, HH, HH, 0, 0, 1.f);
        // LN2 -> y
        ln_kernel<<<MR, blk>>>(p_h, ln2_g + l * HH, ln2_b + l * HH, p_y, nullptr);
        // ff = gelu(y @ W1 + b1)
        gemm_kernel<4, false><<<grid_ff1, blk>>>(p_y, w116 + (size_t)l * HHxFF, b1 + l * FF_,
                                                 nullptr, p_ff, MR, FF_, HH, FF_, 0, 0, 1.f);
        // h += ff @ W2 + b2
        gemm_kernel<3, false><<<grid_proj, blk>>>(p_ff, w216 + (size_t)l * HHxFF, b2 + l * HH,
                                                  p_h, nullptr, MR, HH, FF_, HH, 0, 0, 1.f);
    }
    // final LN -> fp32 output
    ln_kernel<<<MR, blk>>>(p_h, fln_g, fln_b, nullptr, out);
}